// round 4
// baseline (speedup 1.0000x reference)
#include <cuda_runtime.h>
#include <cstdint>

#define D_FEAT      48
#define N_NODES_MAX 100001

// CSR row pointers built each launch from the sorted COO rows array.
__device__ int d_row_ptr[N_NODES_MAX + 1];

// ---------------------------------------------------------------------------
// Phase 1: row_ptr[r] = lower_bound(rows, rows + E, r). rows sorted; 6.4MB
// lives in L2; ~21 binary-search steps, hidden by 100K-thread parallelism.
// ---------------------------------------------------------------------------
__global__ void build_row_ptr_kernel(const int* __restrict__ rows,
                                     int n_edges, int n_nodes)
{
    int r = blockIdx.x * blockDim.x + threadIdx.x;
    if (r > n_nodes) return;
    int lo = 0, hi = n_edges;
    while (lo < hi) {
        int mid = (lo + hi) >> 1;
        if (__ldg(rows + mid) < r) lo = mid + 1;
        else                       hi = mid;
    }
    d_row_ptr[r] = lo;
}

// ---------------------------------------------------------------------------
// Phase 2: 4-lane-group-per-row CSR SpMM, 8 rows per warp.
//   Lane sub (0..3) owns features [sub*12, sub*12+12): 3 float4 accumulators.
//   Per edge per group: uniform __ldg of (col, val) [L1 broadcast within the
//   4-lane group], 3x LDG.128 gather, 12 FFMA.
//   8 independent edge streams per warp -> 4x MLP vs half-warp variant.
//   Loop bound = warp-max degree; finished groups predicated off (no
//   wavefronts generated). No shfl in hot loop, no atomics. Every row stores
//   unconditionally -> no zero-init pass.
// ---------------------------------------------------------------------------
__global__ void __launch_bounds__(256) spmm_csr_group4_kernel(
    const float* __restrict__ x,
    const int*   __restrict__ cols,
    const float* __restrict__ vals,
    float*       __restrict__ out,
    int n_nodes)
{
    const int warp_id = (blockIdx.x * blockDim.x + threadIdx.x) >> 5;
    const int lane    = threadIdx.x & 31;
    const int g       = lane >> 2;          // group 0..7 -> row within warp
    const int sub     = lane & 3;           // lane within group

    const int  row   = warp_id * 8 + g;
    const bool rowok = row < n_nodes;

    int s = 0, e = 0;
    if (rowok) {
        s = d_row_ptr[row];
        e = d_row_ptr[row + 1];
    }
    const int d = e - s;

    // Warp-wide max degree -> uniform trip count.
    int dmax = d;
    #pragma unroll
    for (int off = 16; off; off >>= 1)
        dmax = max(dmax, __shfl_xor_sync(0xffffffffu, dmax, off));

    float4 A0 = make_float4(0.f, 0.f, 0.f, 0.f);
    float4 A1 = make_float4(0.f, 0.f, 0.f, 0.f);
    float4 A2 = make_float4(0.f, 0.f, 0.f, 0.f);

    const int foff = sub * 12;              // 12 floats per lane, 16B aligned

    int i = s;
    #pragma unroll 2
    for (int j = 0; j < dmax; ++j, ++i) {
        const bool act = j < d;
        if (act) {
            const int   c = __ldg(cols + i);   // uniform within 4-lane group
            const float v = __ldg(vals + i);
            const float* xp = x + (size_t)c * D_FEAT + foff;
            const float4 x0 = *reinterpret_cast<const float4*>(xp);
            const float4 x1 = *reinterpret_cast<const float4*>(xp + 4);
            const float4 x2 = *reinterpret_cast<const float4*>(xp + 8);
            A0.x += v * x0.x; A0.y += v * x0.y; A0.z += v * x0.z; A0.w += v * x0.w;
            A1.x += v * x1.x; A1.y += v * x1.y; A1.z += v * x1.z; A1.w += v * x1.w;
            A2.x += v * x2.x; A2.y += v * x2.y; A2.z += v * x2.z; A2.w += v * x2.w;
        }
    }

    if (rowok) {
        float* o = out + (size_t)row * D_FEAT + foff;
        *reinterpret_cast<float4*>(o)     = A0;   // zeros for empty rows
        *reinterpret_cast<float4*>(o + 4) = A1;
        *reinterpret_cast<float4*>(o + 8) = A2;
    }
}

// ---------------------------------------------------------------------------
// kernel_launch: inputs per metadata order: t, x, rows, cols, vals.
// ---------------------------------------------------------------------------
extern "C" void kernel_launch(void* const* d_in, const int* in_sizes, int n_in,
                              void* d_out, int out_size)
{
    const float* x    = (const float*)d_in[1];
    const int*   rows = (const int*)  d_in[2];
    const int*   cols = (const int*)  d_in[3];
    const float* vals = (const float*)d_in[4];
    float*       out  = (float*)d_out;

    const int n_edges = in_sizes[4];
    const int n_nodes = out_size / D_FEAT;

    // Phase 1: CSR row pointers.
    {
        const int threads = 256;
        const int blocks  = (n_nodes + 1 + threads - 1) / threads;
        build_row_ptr_kernel<<<blocks, threads>>>(rows, n_edges, n_nodes);
    }

    // Phase 2: 8-rows-per-warp SpMM.
    {
        const int threads = 256;                           // 8 warps/block
        const int warps   = (n_nodes + 7) / 8;
        const int blocks  = (warps * 32 + threads - 1) / threads;
        spmm_csr_group4_kernel<<<blocks, threads>>>(x, cols, vals, out, n_nodes);
    }
}

// round 5
// speedup vs baseline: 1.0969x; 1.0969x over previous
#include <cuda_runtime.h>
#include <cstdint>

#define D_FEAT      48
#define N_NODES_MAX 100001

// CSR row pointers built each launch from the sorted COO rows array.
__device__ int d_row_ptr[N_NODES_MAX + 1];

// ---------------------------------------------------------------------------
// Phase 1: row_ptr[r] = lower_bound(rows, rows + E, r). rows sorted; lives in
// L2; ~21 binary-search steps, hidden by 100K-thread parallelism.
// ---------------------------------------------------------------------------
__global__ void build_row_ptr_kernel(const int* __restrict__ rows,
                                     int n_edges, int n_nodes)
{
    int r = blockIdx.x * blockDim.x + threadIdx.x;
    if (r > n_nodes) return;
    int lo = 0, hi = n_edges;
    while (lo < hi) {
        int mid = (lo + hi) >> 1;
        if (__ldg(rows + mid) < r) lo = mid + 1;
        else                       hi = mid;
    }
    d_row_ptr[r] = lo;
}

// ---------------------------------------------------------------------------
// Phase 2: half-warp-per-row CSR SpMM with 4-edge vectorized metadata.
//   warp w -> rows {2w, 2w+1}; lanes [0,16) row A, [16,32) row B.
//   Lanes sub=0..11 each own one float4 of features (12 x 16B = 192B row),
//   so one gather LDG.128 covers the full row: 2 cache lines = 2 L1
//   wavefronts per edge (structural minimum).
//   Metadata loaded as int4/float4 (uniform within half -> broadcast):
//   2 instrs per 4 edges, and exposes 4 independent gathers per half per
//   batch (x2 unroll -> ~16 in flight per warp) to hide L2 latency.
//   No atomics; every row stores unconditionally -> no zero-init pass.
// ---------------------------------------------------------------------------
__global__ void __launch_bounds__(256) spmm_csr_hw4_kernel(
    const float* __restrict__ x,
    const int*   __restrict__ cols,
    const float* __restrict__ vals,
    float*       __restrict__ out,
    int n_nodes, int n_edges)
{
    const int warp_id = (blockIdx.x * blockDim.x + threadIdx.x) >> 5;
    const int lane    = threadIdx.x & 31;
    const int half    = lane >> 4;
    const int sub     = lane & 15;
    const bool active = sub < 12;

    const int row = warp_id * 2 + half;
    if (row >= n_nodes) return;

    const int s = d_row_ptr[row];
    const int e = d_row_ptr[row + 1];

    float ax = 0.f, ay = 0.f, az = 0.f, aw = 0.f;
    const int foff = sub * 4;

    #pragma unroll 2
    for (int i = (s & ~3); i < e; i += 4) {
        int4   c4;
        float4 v4;
        if (i + 4 <= n_edges) {                 // safe 16B vector loads
            c4 = __ldg(reinterpret_cast<const int4*>(cols + i));
            v4 = __ldg(reinterpret_cast<const float4*>(vals + i));
        } else {                                // only possible at array end
            c4.x = cols[i];
            c4.y = (i + 1 < n_edges) ? cols[i + 1] : 0;
            c4.z = (i + 2 < n_edges) ? cols[i + 2] : 0;
            c4.w = (i + 3 < n_edges) ? cols[i + 3] : 0;
            v4.x = vals[i];
            v4.y = (i + 1 < n_edges) ? vals[i + 1] : 0.f;
            v4.z = (i + 2 < n_edges) ? vals[i + 2] : 0.f;
            v4.w = (i + 3 < n_edges) ? vals[i + 3] : 0.f;
        }

        // 4 independent predicated gathers + FFMAs.
        if (active && i >= s && i < e) {
            const float4 xv = *reinterpret_cast<const float4*>(
                x + (size_t)c4.x * D_FEAT + foff);
            ax += v4.x * xv.x; ay += v4.x * xv.y;
            az += v4.x * xv.z; aw += v4.x * xv.w;
        }
        if (active && i + 1 >= s && i + 1 < e) {
            const float4 xv = *reinterpret_cast<const float4*>(
                x + (size_t)c4.y * D_FEAT + foff);
            ax += v4.y * xv.x; ay += v4.y * xv.y;
            az += v4.y * xv.z; aw += v4.y * xv.w;
        }
        if (active && i + 2 >= s && i + 2 < e) {
            const float4 xv = *reinterpret_cast<const float4*>(
                x + (size_t)c4.z * D_FEAT + foff);
            ax += v4.z * xv.x; ay += v4.z * xv.y;
            az += v4.z * xv.z; aw += v4.z * xv.w;
        }
        if (active && i + 3 >= s && i + 3 < e) {
            const float4 xv = *reinterpret_cast<const float4*>(
                x + (size_t)c4.w * D_FEAT + foff);
            ax += v4.w * xv.x; ay += v4.w * xv.y;
            az += v4.w * xv.z; aw += v4.w * xv.w;
        }
    }

    if (active) {
        float4* o = reinterpret_cast<float4*>(out + (size_t)row * D_FEAT + foff);
        *o = make_float4(ax, ay, az, aw);       // zeros for empty rows
    }
}

// ---------------------------------------------------------------------------
// kernel_launch: inputs per metadata order: t, x, rows, cols, vals.
// ---------------------------------------------------------------------------
extern "C" void kernel_launch(void* const* d_in, const int* in_sizes, int n_in,
                              void* d_out, int out_size)
{
    const float* x    = (const float*)d_in[1];
    const int*   rows = (const int*)  d_in[2];
    const int*   cols = (const int*)  d_in[3];
    const float* vals = (const float*)d_in[4];
    float*       out  = (float*)d_out;

    const int n_edges = in_sizes[4];
    const int n_nodes = out_size / D_FEAT;

    // Phase 1: CSR row pointers.
    {
        const int threads = 256;
        const int blocks  = (n_nodes + 1 + threads - 1) / threads;
        build_row_ptr_kernel<<<blocks, threads>>>(rows, n_edges, n_nodes);
    }

    // Phase 2: half-warp-per-row SpMM with vectorized metadata.
    {
        const int threads = 256;                           // 8 warps/block
        const int warps   = (n_nodes + 1) / 2;
        const int blocks  = (warps * 32 + threads - 1) / threads;
        spmm_csr_hw4_kernel<<<blocks, threads>>>(x, cols, vals, out,
                                                 n_nodes, n_edges);
    }
}

// round 6
// speedup vs baseline: 1.1776x; 1.0737x over previous
#include <cuda_runtime.h>
#include <cuda_fp16.h>
#include <cstdint>

#define D_FEAT      48
#define XH_STRIDE   64            // halfs per row: 48 data + 16 zero pad = 128B
#define N_NODES_DS  100000        // dataset node count (fixed shape)
#define N_NODES_MAX 100001

// CSR row pointers built each launch from the sorted COO rows array.
__device__ int d_row_ptr[N_NODES_MAX + 1];

// fp16 copy of x, rows padded to 128B so each gather touches exactly 1 line.
__device__ __align__(128) __half d_xh[(size_t)N_NODES_DS * XH_STRIDE];

// ---------------------------------------------------------------------------
// Phase 0: convert x (fp32 [N,48]) -> d_xh (fp16 [N,64], zero-padded).
// One thread per 8-feature chunk: reads two float4, writes one uint4.
// ---------------------------------------------------------------------------
__global__ void convert_x_kernel(const float* __restrict__ x, int n_nodes)
{
    const int tid   = blockIdx.x * blockDim.x + threadIdx.x;
    const int row   = tid >> 3;
    const int chunk = tid & 7;
    if (row >= n_nodes) return;

    uint4 outv;
    if (chunk < 6) {
        const float4 f0 = *reinterpret_cast<const float4*>(
            x + (size_t)row * D_FEAT + chunk * 8);
        const float4 f1 = *reinterpret_cast<const float4*>(
            x + (size_t)row * D_FEAT + chunk * 8 + 4);
        __half2 h0 = __floats2half2_rn(f0.x, f0.y);
        __half2 h1 = __floats2half2_rn(f0.z, f0.w);
        __half2 h2 = __floats2half2_rn(f1.x, f1.y);
        __half2 h3 = __floats2half2_rn(f1.z, f1.w);
        outv.x = *reinterpret_cast<const unsigned*>(&h0);
        outv.y = *reinterpret_cast<const unsigned*>(&h1);
        outv.z = *reinterpret_cast<const unsigned*>(&h2);
        outv.w = *reinterpret_cast<const unsigned*>(&h3);
    } else {
        outv = make_uint4(0, 0, 0, 0);
    }
    *reinterpret_cast<uint4*>(d_xh + (size_t)row * XH_STRIDE + chunk * 8) = outv;
}

// ---------------------------------------------------------------------------
// Phase 1: row_ptr[r] = lower_bound(rows, rows + E, r).
// ---------------------------------------------------------------------------
__global__ void build_row_ptr_kernel(const int* __restrict__ rows,
                                     int n_edges, int n_nodes)
{
    int r = blockIdx.x * blockDim.x + threadIdx.x;
    if (r > n_nodes) return;
    int lo = 0, hi = n_edges;
    while (lo < hi) {
        int mid = (lo + hi) >> 1;
        if (__ldg(rows + mid) < r) lo = mid + 1;
        else                       hi = mid;
    }
    d_row_ptr[r] = lo;
}

// ---------------------------------------------------------------------------
// Phase 2: quarter-warp-per-row CSR SpMM over the fp16 x copy.
//   warp w -> rows {4w..4w+3}; group g = lane>>3, sub = lane&7.
//   Lanes sub=0..5 each own 8 features; gather = one LDG.128 per edge
//   touching exactly ONE 128B line -> 1 L1 wavefront per edge (vs 2 for
//   fp32 192B rows). 4 independent edge streams per warp.
//   fp32 accumulation; plain stores; no atomics; no zero-init pass.
// ---------------------------------------------------------------------------
__global__ void __launch_bounds__(256) spmm_csr_qw_h_kernel(
    const int*   __restrict__ cols,
    const float* __restrict__ vals,
    float*       __restrict__ out,
    int n_nodes)
{
    const int warp_id = (blockIdx.x * blockDim.x + threadIdx.x) >> 5;
    const int lane    = threadIdx.x & 31;
    const int g       = lane >> 3;          // group 0..3 -> row within warp
    const int sub     = lane & 7;           // lane within group
    const bool active = sub < 6;            // 6 lanes x 8 halfs = 48 features

    const int row = warp_id * 4 + g;
    if (row >= n_nodes) return;

    const int s = d_row_ptr[row];
    const int e = d_row_ptr[row + 1];

    float a0 = 0.f, a1 = 0.f, a2 = 0.f, a3 = 0.f;
    const float* dummy0;
    float a4 = 0.f, a5 = 0.f, a6 = 0.f, a7 = 0.f;
    (void)dummy0;

    const size_t hoff = (size_t)sub * 8;    // 8 halfs = 16B per lane

    #pragma unroll 4
    for (int i = s; i < e; ++i) {
        const int   c = __ldg(cols + i);    // uniform within 8-lane group
        const float v = __ldg(vals + i);
        if (active) {
            const uint4 h4 = *reinterpret_cast<const uint4*>(
                d_xh + (size_t)c * XH_STRIDE + hoff);     // LDG.E.128, 1 line
            const float2 f0 = __half22float2(*reinterpret_cast<const __half2*>(&h4.x));
            const float2 f1 = __half22float2(*reinterpret_cast<const __half2*>(&h4.y));
            const float2 f2 = __half22float2(*reinterpret_cast<const __half2*>(&h4.z));
            const float2 f3 = __half22float2(*reinterpret_cast<const __half2*>(&h4.w));
            a0 += v * f0.x; a1 += v * f0.y;
            a2 += v * f1.x; a3 += v * f1.y;
            a4 += v * f2.x; a5 += v * f2.y;
            a6 += v * f3.x; a7 += v * f3.y;
        }
    }

    if (active) {
        float* o = out + (size_t)row * D_FEAT + sub * 8;
        *reinterpret_cast<float4*>(o)     = make_float4(a0, a1, a2, a3);
        *reinterpret_cast<float4*>(o + 4) = make_float4(a4, a5, a6, a7);
    }
}

// ---------------------------------------------------------------------------
// kernel_launch: inputs per metadata order: t, x, rows, cols, vals.
// ---------------------------------------------------------------------------
extern "C" void kernel_launch(void* const* d_in, const int* in_sizes, int n_in,
                              void* d_out, int out_size)
{
    const float* x    = (const float*)d_in[1];
    const int*   rows = (const int*)  d_in[2];
    const int*   cols = (const int*)  d_in[3];
    const float* vals = (const float*)d_in[4];
    float*       out  = (float*)d_out;

    const int n_edges = in_sizes[4];
    const int n_nodes = out_size / D_FEAT;   // dataset: 100000

    // Phase 0: fp16 copy of x with 128B row stride.
    {
        const int threads = 256;
        const int total   = n_nodes * 8;
        const int blocks  = (total + threads - 1) / threads;
        convert_x_kernel<<<blocks, threads>>>(x, n_nodes);
    }

    // Phase 1: CSR row pointers.
    {
        const int threads = 256;
        const int blocks  = (n_nodes + 1 + threads - 1) / threads;
        build_row_ptr_kernel<<<blocks, threads>>>(rows, n_edges, n_nodes);
    }

    // Phase 2: quarter-warp-per-row SpMM on fp16 x.
    {
        const int threads = 256;                           // 8 warps/block
        const int warps   = (n_nodes + 3) / 4;
        const int blocks  = (warps * 32 + threads - 1) / threads;
        spmm_csr_qw_h_kernel<<<blocks, threads>>>(cols, vals, out, n_nodes);
    }
}